// round 6
// baseline (speedup 1.0000x reference)
#include <cuda_runtime.h>
#include <cstdint>

// GHM ranking loss — fused streaming kernel with cp.async (LDGSTS) smem staging.
// Bins via threshold compares on z (no sigmoid): g >= k/10 <=> z > logit(k/10).
// Only bins 5..9 carry loss: per threshold, r=FSET(z>Tk), cnt+=r, loss+=r*loss.
// Each thread runs a private 3-stage cp.async pipeline into smem (self-produced,
// self-consumed -> no block sync in the mainloop). Last-block-done finalize.

#define GHM_THREADS 256
#define GHM_BLOCKS  888   // 148 SMs x 6 (smem allows 6, regs cap at 5)
#define STAGES      3

static __device__ double       g_loss[5];
static __device__ double       g_cnt[5];
static __device__ unsigned int g_done;

__device__ __forceinline__ float fset_gt(float z, float T) {
    float r;
    asm("set.gt.f32.f32 %0, %1, %2;" : "=f"(r) : "f"(z), "f"(T));
    return r;
}

struct Acc { float c[5]; float l[5]; };

__device__ __forceinline__ void ghm_elem(Acc& A, float a, float b, int t) {
    const float T6 = 0.40546510810816444f;   // logit(0.6)
    const float T7 = 0.84729786038720363f;   // logit(0.7)
    const float T8 = 1.38629436111989062f;   // logit(0.8)
    const float T9 = 2.19722457733621939f;   // logit(0.9)

    float d    = a - b;
    int   mask = -t;                                       // t in {0,1}
    int   zi   = __float_as_int(d) ^ (mask & 0x80000000);  // z = t ? -d : d
    float z    = __int_as_float(zi);
    float loss = __int_as_float(zi & mask);                // t ? z : 0 (r gates sign)

    float r5 = fset_gt(z, 0.0f);
    float r6 = fset_gt(z, T6);
    float r7 = fset_gt(z, T7);
    float r8 = fset_gt(z, T8);
    float r9 = fset_gt(z, T9);

    A.c[0] += r5;  A.l[0] = fmaf(r5, loss, A.l[0]);
    A.c[1] += r6;  A.l[1] = fmaf(r6, loss, A.l[1]);
    A.c[2] += r7;  A.l[2] = fmaf(r7, loss, A.l[2]);
    A.c[3] += r8;  A.l[3] = fmaf(r8, loss, A.l[3]);
    A.c[4] += r9;  A.l[4] = fmaf(r9, loss, A.l[4]);
}

__device__ __forceinline__ void ghm_vec(Acc& A, float4 a, float4 b, int4 t) {
    ghm_elem(A, a.x, b.x, t.x);
    ghm_elem(A, a.y, b.y, t.y);
    ghm_elem(A, a.z, b.z, t.z);
    ghm_elem(A, a.w, b.w, t.w);
}

__global__ void __launch_bounds__(GHM_THREADS, 5) ghm_fused(
    const float4* __restrict__ o1,
    const float4* __restrict__ o2,
    const int4*   __restrict__ tg,
    float* __restrict__ out,
    int nvec, int n)
{
    __shared__ float4 s_a[STAGES][GHM_THREADS];
    __shared__ float4 s_b[STAGES][GHM_THREADS];
    __shared__ int4   s_t[STAGES][GHM_THREADS];

    const int tid  = threadIdx.x;
    const int gtid = blockIdx.x * GHM_THREADS + tid;
    const int tot  = gridDim.x * GHM_THREADS;
    const int full = nvec / tot;

    const uint32_t sa0 = (uint32_t)__cvta_generic_to_shared(&s_a[0][tid]);
    const uint32_t sb0 = (uint32_t)__cvta_generic_to_shared(&s_b[0][tid]);
    const uint32_t st0 = (uint32_t)__cvta_generic_to_shared(&s_t[0][tid]);
    const uint32_t STRIDE = GHM_THREADS * 16;   // bytes per stage

    #define GHM_ISSUE(K, STG)                                                   \
        do {                                                                    \
            const int _v = gtid + (K) * tot;                                    \
            asm volatile("cp.async.cg.shared.global [%0], [%1], 16;"            \
                         :: "r"(sa0 + (STG) * STRIDE), "l"(o1 + _v));           \
            asm volatile("cp.async.cg.shared.global [%0], [%1], 16;"            \
                         :: "r"(sb0 + (STG) * STRIDE), "l"(o2 + _v));           \
            asm volatile("cp.async.cg.shared.global [%0], [%1], 16;"            \
                         :: "r"(st0 + (STG) * STRIDE), "l"(tg + _v));           \
        } while (0)

    Acc A;
    #pragma unroll
    for (int i = 0; i < 5; i++) { A.c[i] = 0.f; A.l[i] = 0.f; }

    // Prologue: stages 0,1 (empty commit keeps group accounting uniform)
    if (0 < full) GHM_ISSUE(0, 0);
    asm volatile("cp.async.commit_group;");
    if (1 < full) GHM_ISSUE(1, 1);
    asm volatile("cp.async.commit_group;");

    #pragma unroll 3
    for (int k = 0; k < full; k++) {
        const int stg = k % STAGES;
        if (k + 2 < full) GHM_ISSUE(k + 2, (k + 2) % STAGES);
        asm volatile("cp.async.commit_group;");
        asm volatile("cp.async.wait_group 2;");   // group k complete
        float4 a = s_a[stg][tid];
        float4 b = s_b[stg][tid];
        int4   t = s_t[stg][tid];
        ghm_vec(A, a, b, t);
    }
    asm volatile("cp.async.wait_group 0;");

    // Vector tail (direct loads)
    {
        const int v = gtid + full * tot;
        if (v < nvec) ghm_vec(A, o1[v], o2[v], tg[v]);
    }
    // Scalar tail (n % 4)
    {
        const int idx = nvec * 4 + gtid;
        if (idx < n)
            ghm_elem(A, ((const float*)o1)[idx], ((const float*)o2)[idx],
                     ((const int*)tg)[idx]);
    }

    // Warp reduction
    #pragma unroll
    for (int off = 16; off > 0; off >>= 1) {
        #pragma unroll
        for (int i = 0; i < 5; i++) {
            A.c[i] += __shfl_down_sync(0xffffffffu, A.c[i], off);
            A.l[i] += __shfl_down_sync(0xffffffffu, A.l[i], off);
        }
    }

    __shared__ float sc[GHM_THREADS / 32][5];
    __shared__ float sl[GHM_THREADS / 32][5];
    const int lane = tid & 31;
    const int wrp  = tid >> 5;
    if (lane == 0) {
        #pragma unroll
        for (int i = 0; i < 5; i++) { sc[wrp][i] = A.c[i]; sl[wrp][i] = A.l[i]; }
    }
    __syncthreads();
    if (tid < 5) {
        float C = 0.f, L = 0.f;
        #pragma unroll
        for (int i = 0; i < GHM_THREADS / 32; i++) {
            C += sc[i][tid];
            L += sl[i][tid];
        }
        atomicAdd(&g_cnt[tid], (double)C);
        atomicAdd(&g_loss[tid], (double)L);
    }
    __syncthreads();

    // Last block finalizes and resets state for the next graph replay.
    __shared__ bool s_last;
    if (tid == 0) {
        __threadfence();
        unsigned done = atomicAdd(&g_done, 1u);
        s_last = (done == gridDim.x - 1);
    }
    __syncthreads();
    if (s_last && tid == 0) {
        __threadfence();
        double Av[5], Lv[5];
        #pragma unroll
        for (int i = 0; i < 5; i++) {
            Av[i] = g_cnt[i];
            Lv[i] = g_loss[i];
            g_cnt[i] = 0.0;
            g_loss[i] = 0.0;
        }
        g_done = 0u;
        double res = 0.0;
        #pragma unroll
        for (int i = 0; i < 5; i++) {
            double C = Av[i] - (i < 4 ? Av[i + 1] : 0.0);  // count in bin 5+i
            double S = Lv[i] - (i < 4 ? Lv[i + 1] : 0.0);  // loss sum in bin 5+i
            if (C < 1.0) C = 1.0;
            res += pow(C, -0.75) * S;
        }
        out[0] = (float)(res / (double)n);
    }
}

extern "C" void kernel_launch(void* const* d_in, const int* in_sizes, int n_in,
                              void* d_out, int out_size) {
    const float* o1 = (const float*)d_in[0];
    const float* o2 = (const float*)d_in[1];
    const int*   tg = (const int*)d_in[2];
    const int n = in_sizes[0];
    const int nvec = n >> 2;

    ghm_fused<<<GHM_BLOCKS, GHM_THREADS>>>((const float4*)o1, (const float4*)o2,
                                           (const int4*)tg, (float*)d_out, nvec, n);
}

// round 7
// speedup vs baseline: 1.1468x; 1.1468x over previous
#include <cuda_runtime.h>

// GHM ranking loss — single fused streaming kernel, 2-quad batched loads.
// Bins via threshold compares on z (no sigmoid): g >= k/10 <=> z > logit(k/10).
// Only bins 5..9 carry loss. Per threshold k: r = FSET(z > Tk) in {0.0,1.0},
// cnt_k += r (FADD), loss_k += r*loss (FFMA).
// 6 front-batched LDG.128 per iteration (3 KB in flight per warp) to cover
// DRAM latency. Last-block-done finalize + state reset (graph-replay safe).

#define GHM_THREADS 256
#define GHM_BLOCKS  740   // 148 SMs x 5 resident blocks, single wave

static __device__ double       g_loss[5];
static __device__ double       g_cnt[5];
static __device__ unsigned int g_done;

__device__ __forceinline__ float fset_gt(float z, float T) {
    float r;
    asm("set.gt.f32.f32 %0, %1, %2;" : "=f"(r) : "f"(z), "f"(T));
    return r;
}

struct Acc { float c[5]; float l[5]; };

__device__ __forceinline__ void ghm_elem(Acc& A, float a, float b, int t) {
    const float T6 = 0.40546510810816444f;   // logit(0.6)
    const float T7 = 0.84729786038720363f;   // logit(0.7)
    const float T8 = 1.38629436111989062f;   // logit(0.8)
    const float T9 = 2.19722457733621939f;   // logit(0.9)

    float d    = a - b;
    int   zi   = __float_as_int(d) ^ (t << 31);  // z = t ? -d : d (t in {0,1})
    float z    = __int_as_float(zi);
    float loss = __int_as_float(zi & (-t));      // t ? z : 0 (sign gated by r)

    float r5 = fset_gt(z, 0.0f);
    float r6 = fset_gt(z, T6);
    float r7 = fset_gt(z, T7);
    float r8 = fset_gt(z, T8);
    float r9 = fset_gt(z, T9);

    A.c[0] += r5;  A.l[0] = fmaf(r5, loss, A.l[0]);
    A.c[1] += r6;  A.l[1] = fmaf(r6, loss, A.l[1]);
    A.c[2] += r7;  A.l[2] = fmaf(r7, loss, A.l[2]);
    A.c[3] += r8;  A.l[3] = fmaf(r8, loss, A.l[3]);
    A.c[4] += r9;  A.l[4] = fmaf(r9, loss, A.l[4]);
}

__device__ __forceinline__ void ghm_vec(Acc& A, float4 a, float4 b, int4 t) {
    ghm_elem(A, a.x, b.x, t.x);
    ghm_elem(A, a.y, b.y, t.y);
    ghm_elem(A, a.z, b.z, t.z);
    ghm_elem(A, a.w, b.w, t.w);
}

__global__ void __launch_bounds__(GHM_THREADS, 5) ghm_fused(
    const float4* __restrict__ o1,
    const float4* __restrict__ o2,
    const int4*   __restrict__ tg,
    float* __restrict__ out,
    int nvec, int n)
{
    Acc A;
    #pragma unroll
    for (int i = 0; i < 5; i++) { A.c[i] = 0.f; A.l[i] = 0.f; }

    const int tid  = threadIdx.x;
    const int gtid = blockIdx.x * GHM_THREADS + tid;
    const int tot  = gridDim.x * GHM_THREADS;
    const int full = nvec / tot;

    // Main loop: 2 quads per iteration, 6 independent LDG.128 front-batched.
    int k = 0;
    for (; k + 2 <= full; k += 2) {
        const int v0 = gtid + k * tot;
        const int v1 = v0 + tot;
        float4 a0 = o1[v0];
        float4 b0 = o2[v0];
        int4   t0 = tg[v0];
        float4 a1 = o1[v1];
        float4 b1 = o2[v1];
        int4   t1 = tg[v1];
        ghm_vec(A, a0, b0, t0);
        ghm_vec(A, a1, b1, t1);
    }
    for (; k < full; k++) {
        const int v = gtid + k * tot;
        ghm_vec(A, o1[v], o2[v], tg[v]);
    }
    // Vector tail
    {
        const int v = gtid + full * tot;
        if (v < nvec) ghm_vec(A, o1[v], o2[v], tg[v]);
    }
    // Scalar tail (n % 4)
    {
        const int idx = nvec * 4 + gtid;
        if (idx < n)
            ghm_elem(A, ((const float*)o1)[idx], ((const float*)o2)[idx],
                     ((const int*)tg)[idx]);
    }

    // Warp reduction (10 f32 values)
    #pragma unroll
    for (int off = 16; off > 0; off >>= 1) {
        #pragma unroll
        for (int i = 0; i < 5; i++) {
            A.c[i] += __shfl_down_sync(0xffffffffu, A.c[i], off);
            A.l[i] += __shfl_down_sync(0xffffffffu, A.l[i], off);
        }
    }

    __shared__ float sc[GHM_THREADS / 32][5];
    __shared__ float sl[GHM_THREADS / 32][5];
    const int lane = tid & 31;
    const int wrp  = tid >> 5;
    if (lane == 0) {
        #pragma unroll
        for (int i = 0; i < 5; i++) { sc[wrp][i] = A.c[i]; sl[wrp][i] = A.l[i]; }
    }
    __syncthreads();
    if (tid < 5) {
        float C = 0.f, L = 0.f;
        #pragma unroll
        for (int i = 0; i < GHM_THREADS / 32; i++) {
            C += sc[i][tid];
            L += sl[i][tid];
        }
        atomicAdd(&g_cnt[tid], (double)C);
        atomicAdd(&g_loss[tid], (double)L);
    }
    __syncthreads();

    // Last block finalizes and resets state for the next graph replay.
    __shared__ bool s_last;
    if (tid == 0) {
        __threadfence();
        unsigned done = atomicAdd(&g_done, 1u);
        s_last = (done == gridDim.x - 1);
    }
    __syncthreads();
    if (s_last && tid == 0) {
        __threadfence();
        double Av[5], Lv[5];
        #pragma unroll
        for (int i = 0; i < 5; i++) {
            Av[i] = g_cnt[i];
            Lv[i] = g_loss[i];
            g_cnt[i] = 0.0;
            g_loss[i] = 0.0;
        }
        g_done = 0u;
        double res = 0.0;
        #pragma unroll
        for (int i = 0; i < 5; i++) {
            double C = Av[i] - (i < 4 ? Av[i + 1] : 0.0);  // count in bin 5+i
            double S = Lv[i] - (i < 4 ? Lv[i + 1] : 0.0);  // loss sum in bin 5+i
            if (C < 1.0) C = 1.0;
            res += pow(C, -0.75) * S;
        }
        out[0] = (float)(res / (double)n);
    }
}

extern "C" void kernel_launch(void* const* d_in, const int* in_sizes, int n_in,
                              void* d_out, int out_size) {
    const float* o1 = (const float*)d_in[0];
    const float* o2 = (const float*)d_in[1];
    const int*   tg = (const int*)d_in[2];
    const int n = in_sizes[0];
    const int nvec = n >> 2;

    ghm_fused<<<GHM_BLOCKS, GHM_THREADS>>>((const float4*)o1, (const float4*)o2,
                                           (const int4*)tg, (float*)d_out, nvec, n);
}